// round 5
// baseline (speedup 1.0000x reference)
#include <cuda_runtime.h>
#include <cuda_bf16.h>

#define TILE  256
#define HALO  12
#define KWIN  9
#define DIL   3
#define HD    32
#define NC2   (HD / 2)          /* 16 channel pairs */
#define KV_W  (TILE + 2*HALO)   /* 280 tokens incl. halo */
#define NP    (KV_W / 2)        /* 140 token-pairs per channel-pair row */
#define NSTG  (NC2 * NP)        /* 2240 staging items */

typedef unsigned long long u64;

__device__ __forceinline__ u64 pack2(float a, float b) {
    u64 r; asm("mov.b64 %0, {%1, %2};" : "=l"(r) : "f"(a), "f"(b)); return r;
}
__device__ __forceinline__ void unpack2(u64 p, float& a, float& b) {
    asm("mov.b64 {%0, %1}, %2;" : "=f"(a), "=f"(b) : "l"(p));
}
__device__ __forceinline__ u64 fma2(u64 a, u64 b, u64 c) {
    u64 d; asm("fma.rn.f32x2 %0, %1, %2, %3;" : "=l"(d) : "l"(a), "l"(b), "l"(c)); return d;
}

// bounds-checked float2 load of elements n..n+1 (zero-fill OOB = Unfold padding)
__device__ __forceinline__ float2 ld2(const float* __restrict__ row, int n, int L) {
    if (n >= 0 && n + 1 < L) return *(const float2*)(row + n);
    float2 r;
    r.x = ((unsigned)(n + 0) < (unsigned)L) ? row[n + 0] : 0.f;
    r.y = ((unsigned)(n + 1) < (unsigned)L) ? row[n + 1] : 0.f;
    return r;
}

__global__ __launch_bounds__(TILE, 3)
void dilated_attn_kernel(const float* __restrict__ q,
                         const float* __restrict__ k,
                         const float* __restrict__ v,
                         float* __restrict__ out,
                         int B, int d, int L)
{
    // channel-paired layout: ks[c2][n] holds (k[2c2][n], k[2c2+1][n]) as float2.
    // Staging: vec4 STS at consecutive lane addresses (conflict-free).
    // Compute: LDS.64 stride-2 across lanes (crossbar floor, no penalty).
    __shared__ float2 ks[NC2][KV_W];
    __shared__ float2 vs[NC2][KV_W];

    const int t    = threadIdx.x;
    const int tile = blockIdx.x & 15;          // L/TILE = 16
    const int h    = (blockIdx.x >> 4) & 15;   // 16 heads
    const int b    = blockIdx.x >> 8;          // 4 batches
    const int n0   = tile * TILE;
    const int n    = n0 + t;

    const long chan_base = ((long)b * d + h * HD) * L;
    const float* kb = k + chan_base;
    const float* vb = v + chan_base;
    const float* qb = q + chan_base;

    // ---- prefetch q (packed per channel-pair); overlaps staging DRAM latency ----
    u64 q2[NC2];
    #pragma unroll
    for (int c2 = 0; c2 < NC2; c2++) {
        const float a  = qb[(long)(2 * c2 + 0) * L + n];
        const float bq = qb[(long)(2 * c2 + 1) * L + n];
        q2[c2] = pack2(a, bq);
    }

    // ---- stage K and V (channel-paired, halo zero-filled) ----
    #pragma unroll
    for (int it = 0; it < 9; it++) {
        const int idx = t + it * TILE;
        if (idx < NSTG) {
            const int c2 = idx / NP;
            const int np = idx - c2 * NP;
            const int ng = n0 - HALO + np * 2;
            const long r0 = (long)(2 * c2 + 0) * L;
            const long r1 = (long)(2 * c2 + 1) * L;
            const float2 ka = ld2(kb + r0, ng, L);
            const float2 kc = ld2(kb + r1, ng, L);
            const float2 va = ld2(vb + r0, ng, L);
            const float2 vc = ld2(vb + r1, ng, L);
            // interleave: tokens ng, ng+1 for channels c0,c1
            *(float4*)&ks[c2][np * 2] = make_float4(ka.x, kc.x, ka.y, kc.y);
            *(float4*)&vs[c2][np * 2] = make_float4(va.x, vc.x, va.y, vc.y);
        }
    }
    __syncthreads();

    // ---- QK^T over the 9-wide dilated window (LDS.64 + f32x2 FMA) ----
    u64 acc2[KWIN];
    #pragma unroll
    for (int kk = 0; kk < KWIN; kk++) acc2[kk] = 0ull;

    #pragma unroll
    for (int c2 = 0; c2 < NC2; c2++) {
        const u64 qq = q2[c2];
        const float2* kr = &ks[c2][t];
        #pragma unroll
        for (int kk = 0; kk < KWIN; kk++) {
            const float2 kv2 = kr[DIL * kk];
            acc2[kk] = fma2(qq, pack2(kv2.x, kv2.y), acc2[kk]);
        }
    }

    // ---- softmax over 9 ----
    const float scale = 0.17677669529663687f;   // 32^-0.5
    float s[KWIN];
    float mx = -1e30f;
    #pragma unroll
    for (int kk = 0; kk < KWIN; kk++) {
        float lo, hi; unpack2(acc2[kk], lo, hi);
        s[kk] = (lo + hi) * scale;
        mx = fmaxf(mx, s[kk]);
    }
    float sum = 0.f;
    #pragma unroll
    for (int kk = 0; kk < KWIN; kk++) { s[kk] = __expf(s[kk] - mx); sum += s[kk]; }
    const float inv = 1.f / sum;
    u64 w2[KWIN];
    #pragma unroll
    for (int kk = 0; kk < KWIN; kk++) { const float w = s[kk] * inv; w2[kk] = pack2(w, w); }

    // ---- attn @ V ----
    u64 o2[NC2];
    #pragma unroll
    for (int c2 = 0; c2 < NC2; c2++) o2[c2] = 0ull;

    #pragma unroll
    for (int kk = 0; kk < KWIN; kk++) {
        const u64 ww = w2[kk];
        const int nl = t + DIL * kk;
        #pragma unroll
        for (int c2 = 0; c2 < NC2; c2++) {
            const float2 vv = vs[c2][nl];
            o2[c2] = fma2(ww, pack2(vv.x, vv.y), o2[c2]);
        }
    }

    // ---- store: out[b][0][n][h*32+c] -> one full 128B line per thread ----
    float4* op = (float4*)(out + ((long)b * L + n) * d + h * HD);
    #pragma unroll
    for (int c4 = 0; c4 < HD / 4; c4++) {
        float4 r;
        unpack2(o2[c4 * 2 + 0], r.x, r.y);
        unpack2(o2[c4 * 2 + 1], r.z, r.w);
        op[c4] = r;
    }
}

extern "C" void kernel_launch(void* const* d_in, const int* in_sizes, int n_in,
                              void* d_out, int out_size)
{
    const float* q = (const float*)d_in[0];
    const float* k = (const float*)d_in[1];
    const float* v = (const float*)d_in[2];
    float* out = (float*)d_out;

    const int B = 4, d = 512, L = 4096;
    const int grid = B * (d / HD) * (L / TILE);   // 4*16*16 = 1024
    dilated_attn_kernel<<<grid, TILE>>>(q, k, v, out, B, d, L);
}

// round 6
// speedup vs baseline: 1.0628x; 1.0628x over previous
#include <cuda_runtime.h>
#include <cuda_bf16.h>

#define TILE  128
#define HALO  12
#define KWIN  9
#define DIL   3
#define HD    32
#define NC2   (HD / 2)          /* 16 channel pairs */
#define KV_W  (TILE + 2*HALO)   /* 152 tokens incl. halo */
#define NP    (KV_W / 2)        /* 76 token-pairs per channel-pair row */
#define NSTG  (NC2 * NP)        /* 1216 staging items per matrix */

typedef unsigned long long u64;

__device__ __forceinline__ u64 pack2(float a, float b) {
    u64 r; asm("mov.b64 %0, {%1, %2};" : "=l"(r) : "f"(a), "f"(b)); return r;
}
__device__ __forceinline__ void unpack2(u64 p, float& a, float& b) {
    asm("mov.b64 {%0, %1}, %2;" : "=f"(a), "=f"(b) : "l"(p));
}
__device__ __forceinline__ u64 fma2(u64 a, u64 b, u64 c) {
    u64 d; asm("fma.rn.f32x2 %0, %1, %2, %3;" : "=l"(d) : "l"(a), "l"(b), "l"(c)); return d;
}

// bounds-checked float2 load of elements n..n+1 (zero-fill OOB = Unfold padding)
__device__ __forceinline__ float2 ld2(const float* __restrict__ row, int n, int L) {
    if (n >= 0 && n + 1 < L) return *(const float2*)(row + n);
    float2 r;
    r.x = ((unsigned)(n + 0) < (unsigned)L) ? row[n + 0] : 0.f;
    r.y = ((unsigned)(n + 1) < (unsigned)L) ? row[n + 1] : 0.f;
    return r;
}

// stage one matrix (k or v) into the shared buffer, channel-paired layout:
// buf[c2][nl] = (x[2c2][n0-HALO+nl], x[2c2+1][n0-HALO+nl])
__device__ __forceinline__ void stage(float2 (*buf)[KV_W],
                                      const float* __restrict__ xb,
                                      int t, int n0, int L)
{
    #pragma unroll
    for (int it = 0; it < 10; it++) {
        const int idx = t + it * TILE;
        if (idx < NSTG) {
            const int c2 = idx / NP;
            const int np = idx - c2 * NP;
            const int ng = n0 - HALO + np * 2;
            const float2 a = ld2(xb + (long)(2 * c2 + 0) * L, ng, L);
            const float2 b = ld2(xb + (long)(2 * c2 + 1) * L, ng, L);
            *(float4*)&buf[c2][np * 2] = make_float4(a.x, b.x, a.y, b.y);
        }
    }
}

__global__ __launch_bounds__(TILE, 8)
void dilated_attn_kernel(const float* __restrict__ q,
                         const float* __restrict__ k,
                         const float* __restrict__ v,
                         float* __restrict__ out,
                         int B, int d, int L)
{
    // single buffer, reused K -> V (two-pass). 19.8 KB -> 8 blocks/SM.
    __shared__ float2 kv_s[NC2][KV_W];

    const int t    = threadIdx.x;
    const int tile = blockIdx.x & 31;          // L/TILE = 32
    const int h    = (blockIdx.x >> 5) & 15;   // 16 heads
    const int b    = blockIdx.x >> 9;          // 4 batches
    const int n0   = tile * TILE;
    const int n    = n0 + t;

    const long chan_base = ((long)b * d + h * HD) * L;
    const float* kb = k + chan_base;
    const float* vb = v + chan_base;
    const float* qb = q + chan_base;

    // ---- prefetch q (packed per channel-pair), overlaps K staging latency ----
    u64 q2[NC2];
    #pragma unroll
    for (int c2 = 0; c2 < NC2; c2++) {
        const float a  = qb[(long)(2 * c2 + 0) * L + n];
        const float bq = qb[(long)(2 * c2 + 1) * L + n];
        q2[c2] = pack2(a, bq);
    }

    // ---- pass 1: stage K, compute QK^T ----
    stage(kv_s, kb, t, n0, L);
    __syncthreads();

    u64 acc2[KWIN];
    #pragma unroll
    for (int kk = 0; kk < KWIN; kk++) acc2[kk] = 0ull;

    #pragma unroll
    for (int c2 = 0; c2 < NC2; c2++) {
        const u64 qq = q2[c2];
        const float2* kr = &kv_s[c2][t];
        #pragma unroll
        for (int kk = 0; kk < KWIN; kk++) {
            const float2 kv2 = kr[DIL * kk];
            acc2[kk] = fma2(qq, pack2(kv2.x, kv2.y), acc2[kk]);
        }
    }

    // ---- softmax over 9 ----
    const float scale = 0.17677669529663687f;   // 32^-0.5
    float s[KWIN];
    float mx = -1e30f;
    #pragma unroll
    for (int kk = 0; kk < KWIN; kk++) {
        float lo, hi; unpack2(acc2[kk], lo, hi);
        s[kk] = (lo + hi) * scale;
        mx = fmaxf(mx, s[kk]);
    }
    float sum = 0.f;
    #pragma unroll
    for (int kk = 0; kk < KWIN; kk++) { s[kk] = __expf(s[kk] - mx); sum += s[kk]; }
    const float inv = 1.f / sum;
    u64 w2[KWIN];
    #pragma unroll
    for (int kk = 0; kk < KWIN; kk++) { const float w = s[kk] * inv; w2[kk] = pack2(w, w); }

    // ---- pass 2: restage V over the same buffer, compute attn @ V ----
    __syncthreads();   // all reads of K done
    stage(kv_s, vb, t, n0, L);
    __syncthreads();

    u64 o2[NC2];
    #pragma unroll
    for (int c2 = 0; c2 < NC2; c2++) o2[c2] = 0ull;

    #pragma unroll
    for (int kk = 0; kk < KWIN; kk++) {
        const u64 ww = w2[kk];
        const float2* vr = &kv_s[0][t + DIL * kk];
        #pragma unroll
        for (int c2 = 0; c2 < NC2; c2++) {
            const float2 vv = vr[c2 * KV_W];
            o2[c2] = fma2(ww, pack2(vv.x, vv.y), o2[c2]);
        }
    }

    // ---- store: out[b][0][n][h*32+c] -> one full 128B line per thread ----
    float4* op = (float4*)(out + ((long)b * L + n) * d + h * HD);
    #pragma unroll
    for (int c4 = 0; c4 < HD / 4; c4++) {
        float4 r;
        unpack2(o2[c4 * 2 + 0], r.x, r.y);
        unpack2(o2[c4 * 2 + 1], r.z, r.w);
        op[c4] = r;
    }
}

extern "C" void kernel_launch(void* const* d_in, const int* in_sizes, int n_in,
                              void* d_out, int out_size)
{
    const float* q = (const float*)d_in[0];
    const float* k = (const float*)d_in[1];
    const float* v = (const float*)d_in[2];
    float* out = (float*)d_out;

    const int B = 4, d = 512, L = 4096;
    const int grid = B * (d / HD) * (L / TILE);   // 2048
    dilated_attn_kernel<<<grid, TILE>>>(q, k, v, out, B, d, L);
}